// round 8
// baseline (speedup 1.0000x reference)
#include <cuda_runtime.h>

// Problem constants (fixed by the reference module)
#define N_  16
#define D_  3
#define H_  160
#define W_  160
#define M_  8
#define K_  10
#define P_  15
#define PM_ 7               // (P-1)/2
#define OH_ (H_ - P_ + 1)   // 146
#define OW_ (W_ - P_ + 1)   // 146
#define MK_ (M_ * K_)       // 80
#define PLANE_ (OH_ * OW_)  // 21316

// Strip: 32 cols x 32 rows per warp, rolling vertical lerp, zero predication.
// 5 column bands (last clamped to x0=114) x 5 row groups (last clamped to
// y0=114); overlapped regions write identical values (deterministic).
// Loads batched 4 rows at a time into registers for MLP=16 per warp.
#define HTILE_ 32
#define CB_    5
#define RG_    5
#define STRIPS_PER_PLANE_ (CB_ * RG_)                  // 25
#define TOTAL_STRIPS_ (N_ * MK_ * STRIPS_PER_PLANE_)   // 32000
#define WARPS_PER_BLOCK_ 8
#define NBLOCKS_ (TOTAL_STRIPS_ / WARPS_PER_BLOCK_)    // 4000

__global__ __launch_bounds__(256, 4)   // allow up to 64 regs/thread
void fern_bits_kernel(
    const float* __restrict__ T,
    const float* __restrict__ dx1, const float* __restrict__ dx2,
    const float* __restrict__ dy1, const float* __restrict__ dy2,
    const float* __restrict__ th,  const float* __restrict__ amb,
    const int*   __restrict__ channels,
    float* __restrict__ out)
{
    // ---- strip decode ----
    const int sid = blockIdx.x * WARPS_PER_BLOCK_ + (threadIdx.x >> 5);
    const int nmk = sid / STRIPS_PER_PLANE_;
    const int rem = sid - nmk * STRIPS_PER_PLANE_;
    const int cb  = rem % CB_;
    const int rg  = rem / CB_;

    const int n   = nmk / MK_;
    const int mk  = nmk - n * MK_;
    const int m   = mk / K_;
    const int k   = mk - m * K_;
    const int ch  = channels[k];

    // ---- per-(m,k) parameters (uniform per warp, broadcast loads) ----
    const float a1x = dx1[mk], a2x = dx2[mk];
    const float a1y = dy1[mk], a2y = dy2[mk];
    const float fl1x = floorf(a1x), fl2x = floorf(a2x);
    const float fl1y = floorf(a1y), fl2y = floorf(a2y);
    const float f1x = a1x - fl1x, f2x = a2x - fl2x;
    const float f1y = a1y - fl1y, f2y = a2y - fl2y;
    const float g1x = 1.0f - f1x, g2x = 1.0f - f2x;
    const float g1y  = 1.0f - f1y;
    const float ng2y = -(1.0f - f2y), nf2y = -f2y;
    const int sx1 = PM_ + (int)fl1x, sx2 = PM_ + (int)fl2x;
    const int sy1 = PM_ + (int)fl1y, sy2 = PM_ + (int)fl2y;

    const float thv = th[mk];
    const float pos = amb[(m * 2 + 0) * K_ + k];
    const float neg = amb[(m * 2 + 1) * K_ + k];
    const float inv = 1.0f / (pos - neg + 1e-29f);
    const float c   = -(thv + neg) * inv;   // v = sat(temp*inv + c)

    // ---- lane geometry (no predication: tail strips overlap) ----
    const int lane = threadIdx.x & 31;
    const int x0   = min(cb * 32, OW_ - 32);          // 0,32,64,96,114
    const int y0   = min(rg * HTILE_, OH_ - HTILE_);  // 0,32,64,96,114
    const int x    = x0 + lane;

    // In-bounds: sy,sx in [0,12]; max row = 12 + 114 + 32 = 158 < 160,
    // max col = 12 + 145 + 1 = 158 < 160. No padding needed.
    const float* __restrict__ img = T + ((size_t)(n * D_ + ch)) * (H_ * W_);
    const float* p1 = img + (sy1 + y0) * W_ + sx1 + x;
    const float* p2 = img + (sy2 + y0) * W_ + sx2 + x;
    float* op = out + (size_t)nmk * PLANE_ + y0 * OW_ + x;

    // ---- prologue: horizontal lerp of strip input row 0 ----
    float prev1, prev2;
    {
        const float a0 = __ldg(p1), a1 = __ldg(p1 + 1);
        const float b0 = __ldg(p2), b1 = __ldg(p2 + 1);
        prev1 = g1x * a0 + f1x * a1;
        prev2 = g2x * b0 + f2x * b1;
    }

    // ---- mainloop: 8 groups of 4 rows; loads batched first (MLP=16) ----
    #pragma unroll
    for (int g = 0; g < HTILE_ / 4; g++) {
        float A0[4], A1[4], B0[4], B1[4];
        #pragma unroll
        for (int j = 0; j < 4; j++) {
            const int r = g * 4 + j + 1;            // compile-time offset
            A0[j] = __ldg(p1 + r * W_);
            A1[j] = __ldg(p1 + r * W_ + 1);
            B0[j] = __ldg(p2 + r * W_);
            B1[j] = __ldg(p2 + r * W_ + 1);
        }
        #pragma unroll
        for (int j = 0; j < 4; j++) {
            const float cur1 = g1x * A0[j] + f1x * A1[j];
            const float cur2 = g2x * B0[j] + f2x * B1[j];

            float temp = g1y * prev1;
            temp = fmaf(f1y,  cur1,  temp);
            temp = fmaf(ng2y, prev2, temp);
            temp = fmaf(nf2y, cur2,  temp);
            prev1 = cur1;
            prev2 = cur2;

            if (fabsf(temp) < 1e-5f) temp = 0.0f;
            op[(g * 4 + j) * OW_] = __saturatef(fmaf(temp, inv, c));
        }
    }
}

extern "C" void kernel_launch(void* const* d_in, const int* in_sizes, int n_in,
                              void* d_out, int out_size)
{
    const float* T        = (const float*)d_in[0];
    const float* dx1      = (const float*)d_in[1];
    const float* dx2      = (const float*)d_in[2];
    const float* dy1      = (const float*)d_in[3];
    const float* dy2      = (const float*)d_in[4];
    const float* th       = (const float*)d_in[5];
    const float* amb      = (const float*)d_in[6];
    const int*   channels = (const int*)  d_in[7];
    float* out = (float*)d_out;

    fern_bits_kernel<<<NBLOCKS_, WARPS_PER_BLOCK_ * 32>>>(
        T, dx1, dx2, dy1, dy2, th, amb, channels, out);
}

// round 9
// speedup vs baseline: 1.3392x; 1.3392x over previous
#include <cuda_runtime.h>

// Problem constants (fixed by the reference module)
#define N_  16
#define D_  3
#define H_  160
#define W_  160
#define M_  8
#define K_  10
#define P_  15
#define PM_ 7               // (P-1)/2
#define OH_ (H_ - P_ + 1)   // 146
#define OW_ (W_ - P_ + 1)   // 146
#define MK_ (M_ * K_)       // 80
#define PLANE_ (OH_ * OW_)  // 21316

// Block = (n, k, rg). All 8 m for a given k sample the same (n, channels[k])
// plane: stage 24 input rows in smem once, warp m computes its 10-row band.
// RG=15 row groups (last clamped to y0=136) -> 2400 blocks = 2.03 waves at
// 8 blocks/SM. 5 column bands of 32 (last clamped to x0=114); overlapped
// regions write identical values (deterministic).
#define HTILE_ 10
#define RG_    15
#define SROWS_ 24                      // 10 + 13 tap rows, rounded up
#define SMEM_FLOATS_ (SROWS_ * W_)     // 3840 floats = 15360 B
#define NBLOCKS_ (N_ * K_ * RG_)       // 2400

__global__ __launch_bounds__(256, 8)   // force <=32 regs, 8 blocks/SM
void fern_bits_kernel(
    const float* __restrict__ T,
    const float* __restrict__ dx1, const float* __restrict__ dx2,
    const float* __restrict__ dy1, const float* __restrict__ dy2,
    const float* __restrict__ th,  const float* __restrict__ amb,
    const int*   __restrict__ channels,
    float* __restrict__ out)
{
    __shared__ float splane[SMEM_FLOATS_];

    // ---- block decode: bid = (n*K + k)*RG + rg ----
    const int bid = blockIdx.x;
    const int rg  = bid % RG_;
    const int nk  = bid / RG_;
    const int k   = nk % K_;
    const int n   = nk / K_;
    const int ch  = channels[k];

    const int y0 = min(rg * HTILE_, OH_ - HTILE_);   // 0,10,...,140 -> 136
    // staged plane rows [y0, y0+23]; max = 136+23 = 159 < 160. OK.

    // ---- cooperative staging: linear float4 copy (960 float4s) ----
    const float* __restrict__ img = T + ((size_t)(n * D_ + ch)) * (H_ * W_);
    {
        const float4* __restrict__ g4 = (const float4*)(img + y0 * W_);
        float4* s4 = (float4*)splane;
        for (int i = threadIdx.x; i < SMEM_FLOATS_ / 4; i += 256)
            s4[i] = g4[i];
    }
    __syncthreads();

    // ---- per-warp: one m value ----
    const int m    = threadIdx.x >> 5;
    const int lane = threadIdx.x & 31;
    const int mk   = m * K_ + k;
    const int nmk  = n * MK_ + mk;

    // per-(m,k) parameters (uniform per warp, broadcast loads)
    const float a1x = dx1[mk], a2x = dx2[mk];
    const float a1y = dy1[mk], a2y = dy2[mk];
    const float fl1x = floorf(a1x), fl2x = floorf(a2x);
    const float fl1y = floorf(a1y), fl2y = floorf(a2y);
    const float f1x = a1x - fl1x, f2x = a2x - fl2x;
    const float f1y = a1y - fl1y, f2y = a2y - fl2y;
    const float g1x = 1.0f - f1x, g2x = 1.0f - f2x;
    const float g1y  = 1.0f - f1y;
    const float ng2y = -(1.0f - f2y), nf2y = -f2y;
    const int sx1 = PM_ + (int)fl1x, sx2 = PM_ + (int)fl2x;
    const int sy1 = PM_ + (int)fl1y, sy2 = PM_ + (int)fl2y;

    const float thv = th[mk];
    const float pos = amb[(m * 2 + 0) * K_ + k];
    const float neg = amb[(m * 2 + 1) * K_ + k];
    const float inv = 1.0f / (pos - neg + 1e-29f);
    const float c   = -(thv + neg) * inv;   // v = sat(temp*inv + c)

    // ---- sweep 5 column bands; 10 rolling rows each, fully unrolled ----
    #pragma unroll 1
    for (int cb = 0; cb < 5; cb++) {
        const int x0 = min(cb * 32, OW_ - 32);   // 0,32,64,96,114
        const int x  = x0 + lane;

        // smem tap bases: sy in [0,12], r<=10 -> row <= 22 < 24;
        // sx in [0,12], x <= 145 -> col <= 158 < 160.
        const float* s1 = splane + sy1 * W_ + sx1 + x;
        const float* s2 = splane + sy2 * W_ + sx2 + x;
        float* op = out + (size_t)nmk * PLANE_ + y0 * OW_ + x;

        // prologue: horizontal lerp of band input row 0
        float prev1 = g1x * s1[0] + f1x * s1[1];
        float prev2 = g2x * s2[0] + f2x * s2[1];

        #pragma unroll
        for (int r = 1; r <= HTILE_; r++) {
            const float a0 = s1[r * W_], a1 = s1[r * W_ + 1];
            const float b0 = s2[r * W_], b1 = s2[r * W_ + 1];
            const float cur1 = g1x * a0 + f1x * a1;
            const float cur2 = g2x * b0 + f2x * b1;

            float temp = g1y * prev1;
            temp = fmaf(f1y,  cur1,  temp);
            temp = fmaf(ng2y, prev2, temp);
            temp = fmaf(nf2y, cur2,  temp);
            prev1 = cur1;
            prev2 = cur2;

            if (fabsf(temp) < 1e-5f) temp = 0.0f;
            op[(r - 1) * OW_] = __saturatef(fmaf(temp, inv, c));
        }
    }
}

extern "C" void kernel_launch(void* const* d_in, const int* in_sizes, int n_in,
                              void* d_out, int out_size)
{
    const float* T        = (const float*)d_in[0];
    const float* dx1      = (const float*)d_in[1];
    const float* dx2      = (const float*)d_in[2];
    const float* dy1      = (const float*)d_in[3];
    const float* dy2      = (const float*)d_in[4];
    const float* th       = (const float*)d_in[5];
    const float* amb      = (const float*)d_in[6];
    const int*   channels = (const int*)  d_in[7];
    float* out = (float*)d_out;

    fern_bits_kernel<<<NBLOCKS_, 256>>>(
        T, dx1, dx2, dy1, dy2, th, amb, channels, out);
}